// round 13
// baseline (speedup 1.0000x reference)
#include <cuda_runtime.h>
#include <cuda_fp16.h>
#include <math.h>
#include <cstdint>

#define NT   8192
#define NO   8192
#define FIN  256
#define FOUT 64
#define ALPHA 0.2f

#define KSPLIT 2
#define JPC   (NO / KSPLIT)   // 4096
#define BK    128
#define TILES (JPC / BK)      // 32
#define BM    64
#define THREADS 512

#define WPR   (NO / 32)       // 256 mask words per row

// smem: P 2x16K | H 2x16K | EF 2x1K | ABs 512B
#define PBUF   16384
#define HBUF   16384
#define EFBUF  1024
#define OFF_H  (2 * PBUF)
#define OFF_EF (OFF_H + 2 * HBUF)
#define OFF_AB (OFF_EF + 2 * EFBUF)
#define SM_TOTAL (OFF_AB + 512)          // 68096

// 16B-chunk swizzle within 128B halves: row r, chunk c (0..15)
#define SWC(r, c) ((((c) & 8) | (((c) ^ (r)) & 7)))

// ---- scratch ----
__device__ float  g_wtv[FIN];
__device__ unsigned g_eomax_u;
__device__ float2 g_EFI[NO];                        // interleaved (E_j, F_j)
__device__ __align__(16) __half g_hoTh[FOUT * NO];  // h_o^T fp16
__device__ uint32_t g_mask[NT * WPR];               // adj bitmask, 8MB
__device__ float  g_Dp[KSPLIT * NT * FOUT];
__device__ float  g_l[KSPLIT * NT];

// ---- helpers ----
__device__ __forceinline__ uint32_t smem_u32(const void* p) {
    uint32_t a;
    asm("{ .reg .u64 t; cvta.to.shared.u64 t, %1; cvt.u32.u64 %0, t; }" : "=r"(a) : "l"(p));
    return a;
}
__device__ __forceinline__ uint32_t f2h2(float lo, float hi) {
    __half2 h = __floats2half2_rn(lo, hi);
    return *(uint32_t*)&h;
}
__device__ __forceinline__ unsigned fenc(float x) {
    int s = __float_as_int(x);
    return (s < 0) ? ~(unsigned)s : ((unsigned)s | 0x80000000u);
}
__device__ __forceinline__ float fdec(unsigned u) {
    int s = (u & 0x80000000u) ? (int)(u & 0x7fffffffu) : (int)~u;
    return __int_as_float(s);
}
__device__ __forceinline__ void ldm_x4(uint32_t& r0, uint32_t& r1, uint32_t& r2,
                                       uint32_t& r3, uint32_t addr) {
    asm volatile("ldmatrix.sync.aligned.m8n8.x4.shared.b16 {%0,%1,%2,%3}, [%4];"
                 : "=r"(r0), "=r"(r1), "=r"(r2), "=r"(r3) : "r"(addr));
}
__device__ __forceinline__ void mma_f16(float* d, uint32_t a0, uint32_t a1,
                                        uint32_t a2, uint32_t a3,
                                        uint32_t b0, uint32_t b1) {
    asm volatile(
        "mma.sync.aligned.m16n8k16.row.col.f32.f16.f16.f32 "
        "{%0,%1,%2,%3}, {%4,%5,%6,%7}, {%8,%9}, {%0,%1,%2,%3};"
        : "+f"(d[0]), "+f"(d[1]), "+f"(d[2]), "+f"(d[3])
        : "r"(a0), "r"(a1), "r"(a2), "r"(a3), "r"(b0), "r"(b1));
}

// ---------------------------------------------------------------------------
// pack: adj (int32 0/1, 256MB) -> bitmask (8MB). Pure streaming, max BW.
// One thread per output word: 32 ints = 8 x LDG.128.
// ---------------------------------------------------------------------------
__global__ __launch_bounds__(256) void pack(const int* __restrict__ adj) {
    size_t idx = (size_t)blockIdx.x * 256 + threadIdx.x;   // 0 .. 2M-1
    const int4* src = (const int4*)adj + idx * 8;
    int4 a[8];
#pragma unroll
    for (int k = 0; k < 8; k++) a[k] = __ldcs(src + k);
    uint32_t v = 0;
#pragma unroll
    for (int k = 0; k < 8; k++) {
        v |= (uint32_t)(a[k].x & 1) << (4 * k);
        v |= (uint32_t)(a[k].y & 1) << (4 * k + 1);
        v |= (uint32_t)(a[k].z & 1) << (4 * k + 2);
        v |= (uint32_t)(a[k].w & 1) << (4 * k + 3);
    }
    g_mask[idx] = v;
}

// ---------------------------------------------------------------------------
// prep_w: wtv = W_t @ a_t; zero eomax
// ---------------------------------------------------------------------------
__global__ void prep_w(const float* __restrict__ Wt, const float* __restrict__ a) {
    int k = threadIdx.x;
    if (k == 0) g_eomax_u = 0u;
    float s1 = 0.f;
#pragma unroll
    for (int f = 0; f < FOUT; f++) s1 += Wt[k * FOUT + f] * a[f];
    g_wtv[k] = s1;
}

// ---------------------------------------------------------------------------
// prep_hoT: h_o^T (fp16) + E/F + eomax fused. 32 j-rows per block.
// ---------------------------------------------------------------------------
__global__ __launch_bounds__(256) void prep_hoT(const float* __restrict__ O,
                                                const float* __restrict__ Wo,
                                                const float* __restrict__ a) {
    __shared__ float os[32 * FIN];
    int jb = blockIdx.x * 32, t = threadIdx.x;
    const float4* src = (const float4*)(O + (size_t)jb * FIN);
    float4* dst = (float4*)os;
#pragma unroll
    for (int i = 0; i < 8; i++) dst[t + i * 256] = src[t + i * 256];
    __syncthreads();
    int tj = t >> 5, tc = t & 31;
    float acc[4][2] = {};
#pragma unroll 4
    for (int k = 0; k < FIN; k++) {
        float2 w = *(const float2*)(Wo + k * FOUT + tc * 2);
#pragma unroll
        for (int i = 0; i < 4; i++) {
            float o = os[(tj * 4 + i) * FIN + k];
            acc[i][0] += o * w.x;
            acc[i][1] += o * w.y;
        }
    }
    float ao0 = a[FOUT + tc * 2], ao1 = a[FOUT + tc * 2 + 1];
    float emax = -1e30f;
#pragma unroll
    for (int i = 0; i < 4; i++) {
        float e = acc[i][0] * ao0 + acc[i][1] * ao1;
#pragma unroll
        for (int off = 16; off; off >>= 1) e += __shfl_xor_sync(0xffffffffu, e, off);
        if (tc == 0) {
            g_EFI[jb + tj * 4 + i] = make_float2(expf(e), expf(ALPHA * e));
            emax = fmaxf(emax, e);
        }
    }
    if (tc == 0) atomicMax(&g_eomax_u, fenc(emax));
#pragma unroll
    for (int ci = 0; ci < 2; ci++) {
        int c = tc * 2 + ci;
        uint2 v = make_uint2(f2h2(acc[0][ci], acc[1][ci]),
                             f2h2(acc[2][ci], acc[3][ci]));
        *(uint2*)(g_hoTh + (size_t)c * NO + jb + tj * 4) = v;
    }
}

// ---------------------------------------------------------------------------
// main: 64 rows x 4096 j. adj via 1-bit masks; deep register pipeline.
// ---------------------------------------------------------------------------
extern __shared__ char smc[];

__global__ __launch_bounds__(THREADS, 1) void attn_main(const float* __restrict__ t_input) {
    const int t = threadIdx.x, w = t >> 5, lane = t & 31;
    const int ibase = blockIdx.x * BM;
    const int split = blockIdx.y;
    const uint32_t sb = smem_u32(smc);
    float2* ABs = (float2*)(smc + OFF_AB);

    // ---- prologue: A_i/B_i for this CTA's 64 rows ----
    {
        int r8 = t >> 3, s8 = t & 7;
        const float* xr = t_input + (size_t)(ibase + r8) * FIN + s8 * 32;
        float s = 0.f;
#pragma unroll
        for (int q = 0; q < 8; q++) {
            float4 x = *(const float4*)(xr + q * 4);
            float4 wv = *(const float4*)(g_wtv + s8 * 32 + q * 4);
            s += x.x * wv.x + x.y * wv.y + x.z * wv.z + x.w * wv.w;
        }
        s += __shfl_xor_sync(0xffffffffu, s, 1);
        s += __shfl_xor_sync(0xffffffffu, s, 2);
        s += __shfl_xor_sync(0xffffffffu, s, 4);
        if (s8 == 0) {
            float eomax = fdec(g_eomax_u);
            float x0 = s + eomax;
            float mi = fmaxf(x0, ALPHA * x0);
            ABs[r8] = make_float2(expf(s - mi), expf(ALPHA * s - mi));
        }
    }

    // P-gen: warp w -> rows w*4..+4; lane jg -> j jg*4..+4
    const int rg = w, jg = lane;
    // mask word for (row rg*4+rr, tile): bits (jg&7)*4.. of word tile*4+(jg>>3)
    const uint32_t* mbase = g_mask + (size_t)(ibase + rg * 4) * WPR +
                            split * (JPC / 32) + (jg >> 3);
    const int nsh = (jg & 7) * 4;

    // H-load: thread -> row hn, chunks hc, hc+8
    const int hn = t >> 3, hc = t & 7;
    const __half* hsrc = g_hoTh + (size_t)hn * NO + split * JPC;
    const float* efsrc = (const float*)g_EFI + (size_t)split * JPC * 2;

    // MMA: warp -> m16 (rbase) x n16 (cbase)
    const int rbase = (w >> 2) * 16, cbase = (w & 3) * 16;
    const int gid = lane >> 2, tid = lane & 3;
    const uint32_t bOne = 0x3C003C00u;  // half2(1,1)
    float acc[2][4] = {};
    float acc_l[4] = {};

    // ---- pipeline prologue ----
    {
        uint4 v0 = *(const uint4*)(hsrc + hc * 8);
        uint4 v1 = *(const uint4*)(hsrc + hc * 8 + 64);
        char* hB = smc + OFF_H;
        *(uint4*)(hB + hn * 256 + SWC(hn, hc) * 16) = v0;
        *(uint4*)(hB + hn * 256 + SWC(hn, hc + 8) * 16) = v1;
    }
    if (t < 64) *(float4*)(smc + OFF_EF + t * 16) = *(const float4*)(efsrc + t * 4);
    uint4 hC0, hC1;
    hC0 = *(const uint4*)(hsrc + BK + hc * 8);
    hC1 = *(const uint4*)(hsrc + BK + hc * 8 + 64);
    float4 efC = make_float4(0.f, 0.f, 0.f, 0.f);
    if (t < 64) efC = *(const float4*)(efsrc + BK * 2 + t * 4);
    uint32_t mC[4];
#pragma unroll
    for (int rr = 0; rr < 4; rr++) mC[rr] = __ldg(mbase + rr * WPR);
    __syncthreads();

    float2 ABr[4];
#pragma unroll
    for (int rr = 0; rr < 4; rr++) ABr[rr] = ABs[rg * 4 + rr];

    for (int tile = 0; tile < TILES; tile++) {
        const int jb = tile * BK;
        const int buf = tile & 1;

        // ---- issue all prefetches first ----
        uint32_t mN[4];
        if (tile + 1 < TILES) {
#pragma unroll
            for (int rr = 0; rr < 4; rr++)
                mN[rr] = __ldg(mbase + rr * WPR + (tile + 1) * 4);
        }
        uint4 hN0, hN1;
        float4 efN;
        if (tile + 2 < TILES) {
            hN0 = *(const uint4*)(hsrc + jb + 2 * BK + hc * 8);
            hN1 = *(const uint4*)(hsrc + jb + 2 * BK + hc * 8 + 64);
            if (t < 64) efN = *(const float4*)(efsrc + (tile + 2) * BK * 2 + t * 4);
        }

        // ---- P tile (fp16, swizzled) from mask bits + EF smem ----
        {
            const char* efb = smc + OFF_EF + buf * EFBUF;
            float4 ef0 = *(const float4*)(efb + jg * 32);
            float4 ef1 = *(const float4*)(efb + jg * 32 + 16);
            char* pB = smc + buf * PBUF;
#pragma unroll
            for (int rr = 0; rr < 4; rr++) {
                const float A = ABr[rr].x, B = ABr[rr].y;
                const uint32_t nib = mC[rr] >> nsh;
                float p0 = fmaxf(A * ef0.x, B * ef0.y);
                float p1 = fmaxf(A * ef0.z, B * ef0.w);
                float p2 = fmaxf(A * ef1.x, B * ef1.y);
                float p3 = fmaxf(A * ef1.z, B * ef1.w);
                p0 = __int_as_float(__float_as_int(p0) & -(int)(nib & 1));
                p1 = __int_as_float(__float_as_int(p1) & -(int)((nib >> 1) & 1));
                p2 = __int_as_float(__float_as_int(p2) & -(int)((nib >> 2) & 1));
                p3 = __int_as_float(__float_as_int(p3) & -(int)((nib >> 3) & 1));
                int r = rg * 4 + rr;
                *(uint2*)(pB + r * 256 + SWC(r, jg >> 1) * 16 + (jg & 1) * 8) =
                    make_uint2(f2h2(p0, p1), f2h2(p2, p3));
            }
        }

        // ---- store next tile's H/EF (regs loaded last iteration) ----
        if (tile + 1 < TILES) {
            char* hB = smc + OFF_H + (buf ^ 1) * HBUF;
            *(uint4*)(hB + hn * 256 + SWC(hn, hc) * 16) = hC0;
            *(uint4*)(hB + hn * 256 + SWC(hn, hc + 8) * 16) = hC1;
            if (t < 64) *(float4*)(smc + OFF_EF + (buf ^ 1) * EFBUF + t * 16) = efC;
        }
        __syncthreads();

        // ---- MMA(t): acc += P[16x128] @ H^T[128x16]; ones-col rowsum ----
        const uint32_t pS = sb + buf * PBUF;
        const uint32_t hS = sb + OFF_H + buf * HBUF;
#pragma unroll
        for (int kk = 0; kk < 8; kk++) {
            uint32_t a0, a1, a2, a3;
            {
                int r = rbase + (lane & 15);
                int c = 2 * kk + (lane >> 4);
                ldm_x4(a0, a1, a2, a3, pS + r * 256 + SWC(r, c) * 16);
            }
            uint32_t b0, b1, b2, b3;
            {
                int g = lane >> 3;
                int n = cbase + (g >> 1) * 8 + (lane & 7);
                int c = 2 * kk + (g & 1);
                ldm_x4(b0, b1, b2, b3, hS + n * 256 + SWC(n, c) * 16);
            }
            mma_f16(acc[0], a0, a1, a2, a3, b0, b1);
            mma_f16(acc[1], a0, a1, a2, a3, b2, b3);
            if ((w & 3) == 0) mma_f16(acc_l, a0, a1, a2, a3, bOne, bOne);
        }

        // rotate pipeline regs
#pragma unroll
        for (int rr = 0; rr < 4; rr++) mC[rr] = mN[rr];
        hC0 = hN0; hC1 = hN1; efC = efN;
    }

    // ---- epilogue ----
    float* dp = g_Dp + ((size_t)split * NT + ibase) * FOUT;
#pragma unroll
    for (int nt = 0; nt < 2; nt++) {
        int col = cbase + nt * 8 + 2 * tid;
        *(float2*)(dp + (size_t)(rbase + gid) * FOUT + col) =
            make_float2(acc[nt][0], acc[nt][1]);
        *(float2*)(dp + (size_t)(rbase + gid + 8) * FOUT + col) =
            make_float2(acc[nt][2], acc[nt][3]);
    }
    if ((w & 3) == 0 && tid == 0) {
        g_l[split * NT + ibase + rbase + gid] = acc_l[0];
        g_l[split * NT + ibase + rbase + gid + 8] = acc_l[2];
    }
}

// ---------------------------------------------------------------------------
// combine: 2 outputs per thread, loads front-issued
// ---------------------------------------------------------------------------
__global__ void combine(float* __restrict__ out) {
    int base = (blockIdx.x * 256 + threadIdx.x) * 2;
#pragma unroll
    for (int u = 0; u < 2; u++) {
        int idx = base + u;
        int r = idx >> 4, c4 = idx & 15;
        float4 d0 = *(const float4*)(g_Dp + (size_t)r * FOUT + c4 * 4);
        float4 d1 = *(const float4*)(g_Dp + ((size_t)NT + r) * FOUT + c4 * 4);
        float inv = 1.f / (g_l[r] + g_l[NT + r]);
        float v[4] = {(d0.x + d1.x) * inv, (d0.y + d1.y) * inv,
                      (d0.z + d1.z) * inv, (d0.w + d1.w) * inv};
#pragma unroll
        for (int i = 0; i < 4; i++) v[i] = v[i] > 0.f ? v[i] : expm1f(v[i]);
        *(float4*)(out + (size_t)r * FOUT + c4 * 4) =
            make_float4(v[0], v[1], v[2], v[3]);
    }
}

// ---------------------------------------------------------------------------
extern "C" void kernel_launch(void* const* d_in, const int* in_sizes, int n_in,
                              void* d_out, int out_size) {
    const float* t_input = (const float*)d_in[0];
    const float* o_input = (const float*)d_in[1];
    const float* W_t     = (const float*)d_in[2];
    const float* W_o     = (const float*)d_in[3];
    const float* a       = (const float*)d_in[4];
    const int*   adj     = (const int*)d_in[5];
    float* out = (float*)d_out;

    cudaFuncSetAttribute(attn_main, cudaFuncAttributeMaxDynamicSharedMemorySize,
                         SM_TOTAL);

    pack<<<NT * WPR / 256, 256>>>(adj);
    prep_w<<<1, 256>>>(W_t, a);
    prep_hoT<<<NO / 32, 256>>>(o_input, W_o, a);
    attn_main<<<dim3(NT / BM, KSPLIT), THREADS, SM_TOTAL>>>(t_input);
    combine<<<NT * FOUT / 8 / 256, 256>>>(out);
}

// round 16
// speedup vs baseline: 1.3756x; 1.3756x over previous
#include <cuda_runtime.h>
#include <cuda_fp16.h>
#include <math.h>
#include <cstdint>

#define NT   8192
#define NO   8192
#define FIN  256
#define FOUT 64
#define ALPHA 0.2f

#define KSPLIT 2
#define JPC   (NO / KSPLIT)   // 4096
#define BK    128
#define TILES (JPC / BK)      // 32
#define BM    64
#define THREADS 256

// smem: P 2x16K | H 3x16K | EF 3x1K | AB 512B
#define PBUF   16384
#define HBUF   16384
#define EFBUF  1024
#define OFF_H  (2 * PBUF)                 // 32768
#define OFF_EF (OFF_H + 3 * HBUF)         // 81920
#define OFF_AB (OFF_EF + 3 * EFBUF)       // 84992
#define SM_TOTAL (OFF_AB + 512)           // 85504

// 16B-chunk swizzle within 128B halves: row r, chunk c (0..15)
#define SWC(r, c) ((((c) & 8) | (((c) ^ (r)) & 7)))

// ---- scratch ----
__device__ float  g_wtv[FIN];
__device__ unsigned g_eomax_u;
__device__ __align__(16) float2 g_EFI[NO];          // interleaved (E_j, F_j)
__device__ __align__(16) __half g_hoTh[FOUT * NO];  // h_o^T fp16
__device__ float  g_Dp[KSPLIT * NT * FOUT];
__device__ float  g_l[KSPLIT * NT];

// ---- helpers ----
__device__ __forceinline__ uint32_t smem_u32(const void* p) {
    uint32_t a;
    asm("{ .reg .u64 t; cvta.to.shared.u64 t, %1; cvt.u32.u64 %0, t; }" : "=r"(a) : "l"(p));
    return a;
}
__device__ __forceinline__ uint32_t f2h2(float lo, float hi) {
    __half2 h = __floats2half2_rn(lo, hi);
    return *(uint32_t*)&h;
}
__device__ __forceinline__ unsigned fenc(float x) {
    int s = __float_as_int(x);
    return (s < 0) ? ~(unsigned)s : ((unsigned)s | 0x80000000u);
}
__device__ __forceinline__ float fdec(unsigned u) {
    int s = (u & 0x80000000u) ? (int)(u & 0x7fffffffu) : (int)~u;
    return __int_as_float(s);
}
__device__ __forceinline__ void cp16(uint32_t dst, const void* src) {
    asm volatile("cp.async.cg.shared.global [%0], [%1], 16;" :: "r"(dst), "l"(src));
}
__device__ __forceinline__ void cp_commit() {
    asm volatile("cp.async.commit_group;" ::: "memory");
}
__device__ __forceinline__ void cp_wait1() {
    asm volatile("cp.async.wait_group 1;" ::: "memory");
}
__device__ __forceinline__ void ldm_x4(uint32_t& r0, uint32_t& r1, uint32_t& r2,
                                       uint32_t& r3, uint32_t addr) {
    asm volatile("ldmatrix.sync.aligned.m8n8.x4.shared.b16 {%0,%1,%2,%3}, [%4];"
                 : "=r"(r0), "=r"(r1), "=r"(r2), "=r"(r3) : "r"(addr));
}
__device__ __forceinline__ void mma_f16(float* d, uint32_t a0, uint32_t a1,
                                        uint32_t a2, uint32_t a3,
                                        uint32_t b0, uint32_t b1) {
    asm volatile(
        "mma.sync.aligned.m16n8k16.row.col.f32.f16.f16.f32 "
        "{%0,%1,%2,%3}, {%4,%5,%6,%7}, {%8,%9}, {%0,%1,%2,%3};"
        : "+f"(d[0]), "+f"(d[1]), "+f"(d[2]), "+f"(d[3])
        : "r"(a0), "r"(a1), "r"(a2), "r"(a3), "r"(b0), "r"(b1));
}

// ---------------------------------------------------------------------------
__global__ void prep_w(const float* __restrict__ Wt, const float* __restrict__ a) {
    int k = threadIdx.x;
    if (k == 0) g_eomax_u = 0u;
    float s1 = 0.f;
#pragma unroll
    for (int f = 0; f < FOUT; f++) s1 += Wt[k * FOUT + f] * a[f];
    g_wtv[k] = s1;
}

// ---------------------------------------------------------------------------
// prep_hoT: h_o^T (fp16) + E/F + eomax fused. 32 j-rows per block.
// ---------------------------------------------------------------------------
__global__ __launch_bounds__(256) void prep_hoT(const float* __restrict__ O,
                                                const float* __restrict__ Wo,
                                                const float* __restrict__ a) {
    __shared__ float os[32 * FIN];
    int jb = blockIdx.x * 32, t = threadIdx.x;
    const float4* src = (const float4*)(O + (size_t)jb * FIN);
    float4* dst = (float4*)os;
#pragma unroll
    for (int i = 0; i < 8; i++) dst[t + i * 256] = src[t + i * 256];
    __syncthreads();
    int tj = t >> 5, tc = t & 31;
    float acc[4][2] = {};
#pragma unroll 4
    for (int k = 0; k < FIN; k++) {
        float2 w = *(const float2*)(Wo + k * FOUT + tc * 2);
#pragma unroll
        for (int i = 0; i < 4; i++) {
            float o = os[(tj * 4 + i) * FIN + k];
            acc[i][0] += o * w.x;
            acc[i][1] += o * w.y;
        }
    }
    float ao0 = a[FOUT + tc * 2], ao1 = a[FOUT + tc * 2 + 1];
    float emax = -1e30f;
#pragma unroll
    for (int i = 0; i < 4; i++) {
        float e = acc[i][0] * ao0 + acc[i][1] * ao1;
#pragma unroll
        for (int off = 16; off; off >>= 1) e += __shfl_xor_sync(0xffffffffu, e, off);
        if (tc == 0) {
            g_EFI[jb + tj * 4 + i] = make_float2(expf(e), expf(ALPHA * e));
            emax = fmaxf(emax, e);
        }
    }
    if (tc == 0) atomicMax(&g_eomax_u, fenc(emax));
#pragma unroll
    for (int ci = 0; ci < 2; ci++) {
        int c = tc * 2 + ci;
        uint2 v = make_uint2(f2h2(acc[0][ci], acc[1][ci]),
                             f2h2(acc[2][ci], acc[3][ci]));
        *(uint2*)(g_hoTh + (size_t)c * NO + jb + tj * 4) = v;
    }
}

// ---------------------------------------------------------------------------
// main: 256 threads, BM=64, 8 warps = 4 m16-groups x 2 k-halves, n=64/warp.
// H/EF via cp.async with TRIPLE buffering; two barriers per tile give the
// formally correct cp.async cross-thread visibility.
// ---------------------------------------------------------------------------
extern __shared__ char smc[];

__global__ __launch_bounds__(THREADS, 2) void attn_main(const float* __restrict__ t_input,
                                                        const int* __restrict__ adj) {
    const int t = threadIdx.x, w = t >> 5, lane = t & 31;
    const int ibase = blockIdx.x * BM;
    const int split = blockIdx.y;
    const uint32_t sb = smem_u32(smc);
    float2* ABs = (float2*)(smc + OFF_AB);

    // ---- prologue: A_i/B_i for this CTA's 64 rows (4 threads/row) ----
    {
        int r4 = t >> 2, s4 = t & 3;
        const float* xr = t_input + (size_t)(ibase + r4) * FIN + s4 * 64;
        float s = 0.f;
#pragma unroll
        for (int q = 0; q < 16; q++) {
            float4 x = *(const float4*)(xr + q * 4);
            float4 wv = *(const float4*)(g_wtv + s4 * 64 + q * 4);
            s += x.x * wv.x + x.y * wv.y + x.z * wv.z + x.w * wv.w;
        }
        s += __shfl_xor_sync(0xffffffffu, s, 1);
        s += __shfl_xor_sync(0xffffffffu, s, 2);
        if (s4 == 0) {
            float eomax = fdec(g_eomax_u);
            float x0 = s + eomax;
            float mi = fmaxf(x0, ALPHA * x0);
            ABs[r4] = make_float2(expf(s - mi), expf(ALPHA * s - mi));
        }
    }

    // P-gen mapping: rg = t>>4 -> rows rg*4..+4; jg = t&15 -> j jg*8..+8
    const int rg = t >> 4, jg = t & 15;
    const int* adjb = adj + (size_t)(ibase + rg * 4) * NO + split * JPC + jg * 8;

    // H cp.async mapping: hn = t>>2 (0..63), chunks (t&3)*4..+4
    const int hn = t >> 2, hq = (t & 3) * 4;
    const __half* hsrc = g_hoTh + (size_t)hn * NO + split * JPC;
    const float* efsrc = (const float*)g_EFI + (size_t)split * JPC * 2;

    // MMA mapping: warp -> m16 group (w>>1), k-half (w&1), n64
    const int rbase = (w >> 1) * 16, kh = w & 1;
    const int gid = lane >> 2, tid = lane & 3;
    const uint32_t bOne = 0x3C003C00u;
    float acc[8][4] = {};
    float acc_l[4] = {};

    // ---- pipeline prologue: cp.async tile0 -> buf 0; adj tile0 regs ----
#pragma unroll
    for (int q = 0; q < 4; q++) {
        int c = hq + q;
        cp16(sb + OFF_H + hn * 256 + SWC(hn, c) * 16, hsrc + c * 8);
    }
    if (t < 64) cp16(sb + OFF_EF + t * 16, efsrc + t * 4);
    cp_commit();
    int4 aC[8];
#pragma unroll
    for (int rr = 0; rr < 4; rr++) {
        aC[2 * rr]     = __ldcs((const int4*)(adjb + (size_t)rr * NO));
        aC[2 * rr + 1] = __ldcs((const int4*)(adjb + (size_t)rr * NO + 4));
    }
    __syncthreads();   // ABs visible

    float2 ABr[4];
#pragma unroll
    for (int rr = 0; rr < 4; rr++) ABr[rr] = ABs[rg * 4 + rr];

    int b3 = 0, n3 = 1;   // tile % 3, (tile+1) % 3
    for (int tile = 0; tile < TILES; tile++) {
        const int jb = tile * BK;
        const int buf = tile & 1;

        // ---- cp.async tile+1 -> buf (tile+1)%3 (disjoint from any reader) ----
        if (tile + 1 < TILES) {
#pragma unroll
            for (int q = 0; q < 4; q++) {
                int c = hq + q;
                cp16(sb + OFF_H + n3 * HBUF + hn * 256 + SWC(hn, c) * 16,
                     hsrc + jb + BK + c * 8);
            }
            if (t < 64)
                cp16(sb + OFF_EF + n3 * EFBUF + t * 16, efsrc + (jb + BK) * 2 + t * 4);
        }
        cp_commit();
        cp_wait1();          // own tile-t groups complete
        __syncthreads();     // ALL threads' tile-t copies complete & visible

        // ---- P tile (fp16, swizzled); adj t+1 prefetch overwrites in place ----
        {
            const char* efb = smc + OFF_EF + b3 * EFBUF;
            float4 ef0 = *(const float4*)(efb + jg * 64);
            float4 ef1 = *(const float4*)(efb + jg * 64 + 16);
            float4 ef2 = *(const float4*)(efb + jg * 64 + 32);
            float4 ef3 = *(const float4*)(efb + jg * 64 + 48);
            char* pB = smc + buf * PBUF;
#pragma unroll
            for (int rr = 0; rr < 4; rr++) {
                const float A = ABr[rr].x, B = ABr[rr].y;
                int4 a0 = aC[2 * rr], a1 = aC[2 * rr + 1];
                float p0 = fmaxf(A * ef0.x, B * ef0.y);
                float p1 = fmaxf(A * ef0.z, B * ef0.w);
                float p2 = fmaxf(A * ef1.x, B * ef1.y);
                float p3 = fmaxf(A * ef1.z, B * ef1.w);
                float p4 = fmaxf(A * ef2.x, B * ef2.y);
                float p5 = fmaxf(A * ef2.z, B * ef2.w);
                float p6 = fmaxf(A * ef3.x, B * ef3.y);
                float p7 = fmaxf(A * ef3.z, B * ef3.w);
                p0 = __int_as_float(__float_as_int(p0) & (-a0.x));
                p1 = __int_as_float(__float_as_int(p1) & (-a0.y));
                p2 = __int_as_float(__float_as_int(p2) & (-a0.z));
                p3 = __int_as_float(__float_as_int(p3) & (-a0.w));
                p4 = __int_as_float(__float_as_int(p4) & (-a1.x));
                p5 = __int_as_float(__float_as_int(p5) & (-a1.y));
                p6 = __int_as_float(__float_as_int(p6) & (-a1.z));
                p7 = __int_as_float(__float_as_int(p7) & (-a1.w));
                int r = rg * 4 + rr;
                *(uint4*)(pB + r * 256 + SWC(r, jg) * 16) =
                    make_uint4(f2h2(p0, p1), f2h2(p2, p3), f2h2(p4, p5), f2h2(p6, p7));
                if (tile + 1 < TILES) {
                    aC[2 * rr]     = __ldcs((const int4*)(adjb + (size_t)rr * NO + jb + BK));
                    aC[2 * rr + 1] = __ldcs((const int4*)(adjb + (size_t)rr * NO + jb + BK + 4));
                }
            }
        }
        __syncthreads();     // P tile visible before ldmatrix

        // ---- MMA(t): warp does m16 x n64 over its k-half (k64) ----
        const uint32_t pS = sb + buf * PBUF;
        const uint32_t hS = sb + OFF_H + b3 * HBUF;
#pragma unroll
        for (int kk = 0; kk < 4; kk++) {
            uint32_t a0, a1, a2, a3;
            {
                int r = rbase + (lane & 15);
                int c = kh * 8 + 2 * kk + (lane >> 4);
                ldm_x4(a0, a1, a2, a3, pS + r * 256 + SWC(r, c) * 16);
            }
            int g = lane >> 3;
            int cB = kh * 8 + 2 * kk + (g & 1);
#pragma unroll
            for (int nt = 0; nt < 4; nt++) {
                uint32_t b0, b1, b2, b3r;
                int n = nt * 16 + (g >> 1) * 8 + (lane & 7);
                ldm_x4(b0, b1, b2, b3r, hS + n * 256 + SWC(n, cB) * 16);
                mma_f16(acc[2 * nt], a0, a1, a2, a3, b0, b1);
                mma_f16(acc[2 * nt + 1], a0, a1, a2, a3, b2, b3r);
            }
            mma_f16(acc_l, a0, a1, a2, a3, bOne, bOne);
        }

        b3 = n3;
        n3 = (n3 == 2) ? 0 : n3 + 1;
    }

    // ---- epilogue: reduce the two k-halves via smem ----
    float* ds = (float*)smc;                   // 64x64 fp32 in P buf0 (last P buf was 1)
    float* lr = (float*)(smc + OFF_EF);        // EF buf0 (last EF buf used was 1)
    if (kh == 1) {
#pragma unroll
        for (int i = 0; i < 8; i++) {
            int col = i * 8 + 2 * tid;
            *(float2*)(ds + (rbase + gid) * FOUT + col) =
                make_float2(acc[i][0], acc[i][1]);
            *(float2*)(ds + (rbase + gid + 8) * FOUT + col) =
                make_float2(acc[i][2], acc[i][3]);
        }
        if (tid == 0) {
            lr[rbase + gid] = acc_l[0];
            lr[rbase + gid + 8] = acc_l[2];
        }
    }
    __syncthreads();
    if (kh == 0) {
        float* dp = g_Dp + ((size_t)split * NT + ibase) * FOUT;
#pragma unroll
        for (int i = 0; i < 8; i++) {
            int col = i * 8 + 2 * tid;
            float2 v0 = *(const float2*)(ds + (rbase + gid) * FOUT + col);
            float2 v1 = *(const float2*)(ds + (rbase + gid + 8) * FOUT + col);
            *(float2*)(dp + (size_t)(rbase + gid) * FOUT + col) =
                make_float2(acc[i][0] + v0.x, acc[i][1] + v0.y);
            *(float2*)(dp + (size_t)(rbase + gid + 8) * FOUT + col) =
                make_float2(acc[i][2] + v1.x, acc[i][3] + v1.y);
        }
        if (tid == 0) {
            g_l[split * NT + ibase + rbase + gid] = acc_l[0] + lr[rbase + gid];
            g_l[split * NT + ibase + rbase + gid + 8] = acc_l[2] + lr[rbase + gid + 8];
        }
    }
}

// ---------------------------------------------------------------------------
__global__ void combine(float* __restrict__ out) {
    int base = (blockIdx.x * 256 + threadIdx.x) * 2;
#pragma unroll
    for (int u = 0; u < 2; u++) {
        int idx = base + u;
        int r = idx >> 4, c4 = idx & 15;
        float4 d0 = *(const float4*)(g_Dp + (size_t)r * FOUT + c4 * 4);
        float4 d1 = *(const float4*)(g_Dp + ((size_t)NT + r) * FOUT + c4 * 4);
        float inv = 1.f / (g_l[r] + g_l[NT + r]);
        float v[4] = {(d0.x + d1.x) * inv, (d0.y + d1.y) * inv,
                      (d0.z + d1.z) * inv, (d0.w + d1.w) * inv};
#pragma unroll
        for (int i = 0; i < 4; i++) v[i] = v[i] > 0.f ? v[i] : expm1f(v[i]);
        *(float4*)(out + (size_t)r * FOUT + c4 * 4) =
            make_float4(v[0], v[1], v[2], v[3]);
    }
}

// ---------------------------------------------------------------------------
extern "C" void kernel_launch(void* const* d_in, const int* in_sizes, int n_in,
                              void* d_out, int out_size) {
    const float* t_input = (const float*)d_in[0];
    const float* o_input = (const float*)d_in[1];
    const float* W_t     = (const float*)d_in[2];
    const float* W_o     = (const float*)d_in[3];
    const float* a       = (const float*)d_in[4];
    const int*   adj     = (const int*)d_in[5];
    float* out = (float*)d_out;

    cudaFuncSetAttribute(attn_main, cudaFuncAttributeMaxDynamicSharedMemorySize,
                         SM_TOTAL);

    prep_w<<<1, 256>>>(W_t, a);
    prep_hoT<<<NO / 32, 256>>>(o_input, W_o, a);
    attn_main<<<dim3(NT / BM, KSPLIT), THREADS, SM_TOTAL>>>(t_input, adj);
    combine<<<NT * FOUT / 8 / 256, 256>>>(out);
}

// round 17
// speedup vs baseline: 1.4217x; 1.0335x over previous
#include <cuda_runtime.h>
#include <cuda_fp16.h>
#include <math.h>
#include <cstdint>

#define NT   8192
#define NO   8192
#define FIN  256
#define FOUT 64
#define ALPHA 0.2f

#define KSPLIT 2
#define JPC   (NO / KSPLIT)   // 4096
#define BK    128
#define TILES (JPC / BK)      // 32
#define BM    64
#define THREADS 256

// smem: P 2x16K | H 3x16K | EF 3x1K | AB 512B
#define PBUF   16384
#define HBUF   16384
#define EFBUF  1024
#define OFF_H  (2 * PBUF)                 // 32768
#define OFF_EF (OFF_H + 3 * HBUF)         // 81920
#define OFF_AB (OFF_EF + 3 * EFBUF)       // 84992
#define SM_TOTAL (OFF_AB + 512)           // 85504

// 16B-chunk swizzle within 128B halves: row r, chunk c (0..15)
#define SWC(r, c) ((((c) & 8) | (((c) ^ (r)) & 7)))

// ---- scratch ----
__device__ float  g_wtv[FIN];
__device__ unsigned g_eomax_u;
__device__ __align__(16) float2 g_EFI[NO];          // interleaved (E_j, F_j)
__device__ __align__(16) __half g_hoTh[FOUT * NO];  // h_o^T fp16
__device__ float  g_Dp[KSPLIT * NT * FOUT];
__device__ float  g_l[KSPLIT * NT];

// ---- helpers ----
__device__ __forceinline__ uint32_t smem_u32(const void* p) {
    uint32_t a;
    asm("{ .reg .u64 t; cvta.to.shared.u64 t, %1; cvt.u32.u64 %0, t; }" : "=r"(a) : "l"(p));
    return a;
}
__device__ __forceinline__ uint32_t f2h2(float lo, float hi) {
    __half2 h = __floats2half2_rn(lo, hi);
    return *(uint32_t*)&h;
}
__device__ __forceinline__ unsigned fenc(float x) {
    int s = __float_as_int(x);
    return (s < 0) ? ~(unsigned)s : ((unsigned)s | 0x80000000u);
}
__device__ __forceinline__ float fdec(unsigned u) {
    int s = (u & 0x80000000u) ? (int)(u & 0x7fffffffu) : (int)~u;
    return __int_as_float(s);
}
__device__ __forceinline__ void cp16(uint32_t dst, const void* src) {
    asm volatile("cp.async.cg.shared.global [%0], [%1], 16;" :: "r"(dst), "l"(src));
}
__device__ __forceinline__ void cp_commit() {
    asm volatile("cp.async.commit_group;" ::: "memory");
}
__device__ __forceinline__ void cp_wait1() {
    asm volatile("cp.async.wait_group 1;" ::: "memory");
}
__device__ __forceinline__ void cp_wait0() {
    asm volatile("cp.async.wait_group 0;" ::: "memory");
}
__device__ __forceinline__ void ldm_x4(uint32_t& r0, uint32_t& r1, uint32_t& r2,
                                       uint32_t& r3, uint32_t addr) {
    asm volatile("ldmatrix.sync.aligned.m8n8.x4.shared.b16 {%0,%1,%2,%3}, [%4];"
                 : "=r"(r0), "=r"(r1), "=r"(r2), "=r"(r3) : "r"(addr));
}
__device__ __forceinline__ void mma_f16(float* d, uint32_t a0, uint32_t a1,
                                        uint32_t a2, uint32_t a3,
                                        uint32_t b0, uint32_t b1) {
    asm volatile(
        "mma.sync.aligned.m16n8k16.row.col.f32.f16.f16.f32 "
        "{%0,%1,%2,%3}, {%4,%5,%6,%7}, {%8,%9}, {%0,%1,%2,%3};"
        : "+f"(d[0]), "+f"(d[1]), "+f"(d[2]), "+f"(d[3])
        : "r"(a0), "r"(a1), "r"(a2), "r"(a3), "r"(b0), "r"(b1));
}

// ---------------------------------------------------------------------------
__global__ void prep_w(const float* __restrict__ Wt, const float* __restrict__ a) {
    int k = threadIdx.x;
    if (k == 0) g_eomax_u = 0u;
    float s1 = 0.f;
#pragma unroll
    for (int f = 0; f < FOUT; f++) s1 += Wt[k * FOUT + f] * a[f];
    g_wtv[k] = s1;
}

// ---------------------------------------------------------------------------
// prep_hoT: h_o^T (fp16) + E/F + eomax fused. 32 j-rows per block.
// ---------------------------------------------------------------------------
__global__ __launch_bounds__(256) void prep_hoT(const float* __restrict__ O,
                                                const float* __restrict__ Wo,
                                                const float* __restrict__ a) {
    __shared__ float os[32 * FIN];
    int jb = blockIdx.x * 32, t = threadIdx.x;
    const float4* src = (const float4*)(O + (size_t)jb * FIN);
    float4* dst = (float4*)os;
#pragma unroll
    for (int i = 0; i < 8; i++) dst[t + i * 256] = src[t + i * 256];
    __syncthreads();
    int tj = t >> 5, tc = t & 31;
    float acc[4][2] = {};
#pragma unroll 4
    for (int k = 0; k < FIN; k++) {
        float2 w = *(const float2*)(Wo + k * FOUT + tc * 2);
#pragma unroll
        for (int i = 0; i < 4; i++) {
            float o = os[(tj * 4 + i) * FIN + k];
            acc[i][0] += o * w.x;
            acc[i][1] += o * w.y;
        }
    }
    float ao0 = a[FOUT + tc * 2], ao1 = a[FOUT + tc * 2 + 1];
    float emax = -1e30f;
#pragma unroll
    for (int i = 0; i < 4; i++) {
        float e = acc[i][0] * ao0 + acc[i][1] * ao1;
#pragma unroll
        for (int off = 16; off; off >>= 1) e += __shfl_xor_sync(0xffffffffu, e, off);
        if (tc == 0) {
            g_EFI[jb + tj * 4 + i] = make_float2(expf(e), expf(ALPHA * e));
            emax = fmaxf(emax, e);
        }
    }
    if (tc == 0) atomicMax(&g_eomax_u, fenc(emax));
#pragma unroll
    for (int ci = 0; ci < 2; ci++) {
        int c = tc * 2 + ci;
        uint2 v = make_uint2(f2h2(acc[0][ci], acc[1][ci]),
                             f2h2(acc[2][ci], acc[3][ci]));
        *(uint2*)(g_hoTh + (size_t)c * NO + jb + tj * 4) = v;
    }
}

// ---------------------------------------------------------------------------
// main: SINGLE barrier per tile. Per tile:
//   P-gen(t) [EF smem t%3, adj regs] -> P[t&1]; adj(t+1) reload;
//   cp H(t+1)->(t+1)%3, EF(t+2)->(t+2)%3; commit; wait1; sync; MMA(t).
// MMA(t) flows barrier-free into P-gen(t+1) -> tensor/LSU overlap.
// ---------------------------------------------------------------------------
extern __shared__ char smc[];

__global__ __launch_bounds__(THREADS, 2) void attn_main(const float* __restrict__ t_input,
                                                        const int* __restrict__ adj) {
    const int t = threadIdx.x, w = t >> 5, lane = t & 31;
    const int ibase = blockIdx.x * BM;
    const int split = blockIdx.y;
    const uint32_t sb = smem_u32(smc);
    float2* ABs = (float2*)(smc + OFF_AB);

    // ---- prologue: A_i/B_i for this CTA's 64 rows (4 threads/row) ----
    {
        int r4 = t >> 2, s4 = t & 3;
        const float* xr = t_input + (size_t)(ibase + r4) * FIN + s4 * 64;
        float s = 0.f;
#pragma unroll
        for (int q = 0; q < 16; q++) {
            float4 x = *(const float4*)(xr + q * 4);
            float4 wv = *(const float4*)(g_wtv + s4 * 64 + q * 4);
            s += x.x * wv.x + x.y * wv.y + x.z * wv.z + x.w * wv.w;
        }
        s += __shfl_xor_sync(0xffffffffu, s, 1);
        s += __shfl_xor_sync(0xffffffffu, s, 2);
        if (s4 == 0) {
            float eomax = fdec(g_eomax_u);
            float x0 = s + eomax;
            float mi = fmaxf(x0, ALPHA * x0);
            ABs[r4] = make_float2(expf(s - mi), expf(ALPHA * s - mi));
        }
    }

    // P-gen mapping: rg = t>>4 -> rows rg*4..+4; jg = t&15 -> j jg*8..+8
    const int rg = t >> 4, jg = t & 15;
    const int* adjb = adj + (size_t)(ibase + rg * 4) * NO + split * JPC + jg * 8;

    // H cp.async mapping: hn = t>>2 (0..63), chunks (t&3)*4..+4
    const int hn = t >> 2, hq = (t & 3) * 4;
    const __half* hsrc = g_hoTh + (size_t)hn * NO + split * JPC;
    const float* efsrc = (const float*)g_EFI + (size_t)split * JPC * 2;

    // MMA mapping: warp -> m16 group (w>>1), k-half (w&1), n64
    const int rbase = (w >> 1) * 16, kh = w & 1;
    const int gid = lane >> 2, tid = lane & 3;
    const uint32_t bOne = 0x3C003C00u;
    float acc[8][4] = {};
    float acc_l[4] = {};

    // ---- pipeline prologue: group P0 = {H(0)->b0, EF(0)->b0, EF(1)->b1} ----
#pragma unroll
    for (int q = 0; q < 4; q++) {
        int c = hq + q;
        cp16(sb + OFF_H + hn * 256 + SWC(hn, c) * 16, hsrc + c * 8);
    }
    if (t < 64) {
        cp16(sb + OFF_EF + t * 16, efsrc + t * 4);
        cp16(sb + OFF_EF + EFBUF + t * 16, efsrc + BK * 2 + t * 4);
    }
    cp_commit();
    int4 aC[8];
#pragma unroll
    for (int rr = 0; rr < 4; rr++) {
        aC[2 * rr]     = __ldcs((const int4*)(adjb + (size_t)rr * NO));
        aC[2 * rr + 1] = __ldcs((const int4*)(adjb + (size_t)rr * NO + 4));
    }
    cp_wait0();
    __syncthreads();   // ABs + H(0)/EF(0)/EF(1) visible to all

    float2 ABr[4];
#pragma unroll
    for (int rr = 0; rr < 4; rr++) ABr[rr] = ABs[rg * 4 + rr];

    int b3 = 0;        // t % 3
    for (int tile = 0; tile < TILES; tile++) {
        const int jb = tile * BK;
        const int buf = tile & 1;
        const int n3 = (b3 == 2) ? 0 : b3 + 1;       // (t+1)%3
        const int m3 = (n3 == 2) ? 0 : n3 + 1;       // (t+2)%3

        // ---- P tile (fp16, swizzled); adj t+1 reload in place ----
        {
            const char* efb = smc + OFF_EF + b3 * EFBUF;
            float4 ef0 = *(const float4*)(efb + jg * 64);
            float4 ef1 = *(const float4*)(efb + jg * 64 + 16);
            float4 ef2 = *(const float4*)(efb + jg * 64 + 32);
            float4 ef3 = *(const float4*)(efb + jg * 64 + 48);
            char* pB = smc + buf * PBUF;
#pragma unroll
            for (int rr = 0; rr < 4; rr++) {
                const float A = ABr[rr].x, B = ABr[rr].y;
                int4 a0 = aC[2 * rr], a1 = aC[2 * rr + 1];
                float p0 = fmaxf(A * ef0.x, B * ef0.y);
                float p1 = fmaxf(A * ef0.z, B * ef0.w);
                float p2 = fmaxf(A * ef1.x, B * ef1.y);
                float p3 = fmaxf(A * ef1.z, B * ef1.w);
                float p4 = fmaxf(A * ef2.x, B * ef2.y);
                float p5 = fmaxf(A * ef2.z, B * ef2.w);
                float p6 = fmaxf(A * ef3.x, B * ef3.y);
                float p7 = fmaxf(A * ef3.z, B * ef3.w);
                p0 = __int_as_float(__float_as_int(p0) & (-a0.x));
                p1 = __int_as_float(__float_as_int(p1) & (-a0.y));
                p2 = __int_as_float(__float_as_int(p2) & (-a0.z));
                p3 = __int_as_float(__float_as_int(p3) & (-a0.w));
                p4 = __int_as_float(__float_as_int(p4) & (-a1.x));
                p5 = __int_as_float(__float_as_int(p5) & (-a1.y));
                p6 = __int_as_float(__float_as_int(p6) & (-a1.z));
                p7 = __int_as_float(__float_as_int(p7) & (-a1.w));
                int r = rg * 4 + rr;
                *(uint4*)(pB + r * 256 + SWC(r, jg) * 16) =
                    make_uint4(f2h2(p0, p1), f2h2(p2, p3), f2h2(p4, p5), f2h2(p6, p7));
                if (tile + 1 < TILES) {
                    aC[2 * rr]     = __ldcs((const int4*)(adjb + (size_t)rr * NO + jb + BK));
                    aC[2 * rr + 1] = __ldcs((const int4*)(adjb + (size_t)rr * NO + jb + BK + 4));
                }
            }
        }

        // ---- cp.async group t: H(t+1), EF(t+2) ----
        if (tile + 1 < TILES) {
#pragma unroll
            for (int q = 0; q < 4; q++) {
                int c = hq + q;
                cp16(sb + OFF_H + n3 * HBUF + hn * 256 + SWC(hn, c) * 16,
                     hsrc + jb + BK + c * 8);
            }
            if (t < 64 && tile + 2 < TILES)
                cp16(sb + OFF_EF + m3 * EFBUF + t * 16,
                     efsrc + (jb + 2 * BK) * 2 + t * 4);
        }
        cp_commit();
        cp_wait1();          // group t-1 (H(t), EF(t+1)) complete in this thread
        __syncthreads();     // ...and in ALL threads; P(t) visible too

        // ---- MMA(t): warp does m16 x n64 over its k-half (k64) ----
        const uint32_t pS = sb + buf * PBUF;
        const uint32_t hS = sb + OFF_H + b3 * HBUF;
#pragma unroll
        for (int kk = 0; kk < 4; kk++) {
            uint32_t a0, a1, a2, a3;
            {
                int r = rbase + (lane & 15);
                int c = kh * 8 + 2 * kk + (lane >> 4);
                ldm_x4(a0, a1, a2, a3, pS + r * 256 + SWC(r, c) * 16);
            }
            int g = lane >> 3;
            int cB = kh * 8 + 2 * kk + (g & 1);
#pragma unroll
            for (int nt = 0; nt < 4; nt++) {
                uint32_t b0, b1, b2, b3r;
                int n = nt * 16 + (g >> 1) * 8 + (lane & 7);
                ldm_x4(b0, b1, b2, b3r, hS + n * 256 + SWC(n, cB) * 16);
                mma_f16(acc[2 * nt], a0, a1, a2, a3, b0, b1);
                mma_f16(acc[2 * nt + 1], a0, a1, a2, a3, b2, b3r);
            }
            mma_f16(acc_l, a0, a1, a2, a3, bOne, bOne);
        }

        b3 = n3;
    }

    // ---- epilogue: reduce the two k-halves via smem ----
    // Last P written = buf 1 -> P buf0 free; EF bufs not read by MMA -> lr safe.
    float* ds = (float*)smc;
    float* lr = (float*)(smc + OFF_EF);
    if (kh == 1) {
#pragma unroll
        for (int i = 0; i < 8; i++) {
            int col = i * 8 + 2 * tid;
            *(float2*)(ds + (rbase + gid) * FOUT + col) =
                make_float2(acc[i][0], acc[i][1]);
            *(float2*)(ds + (rbase + gid + 8) * FOUT + col) =
                make_float2(acc[i][2], acc[i][3]);
        }
        if (tid == 0) {
            lr[rbase + gid] = acc_l[0];
            lr[rbase + gid + 8] = acc_l[2];
        }
    }
    __syncthreads();
    if (kh == 0) {
        float* dp = g_Dp + ((size_t)split * NT + ibase) * FOUT;
#pragma unroll
        for (int i = 0; i < 8; i++) {
            int col = i * 8 + 2 * tid;
            float2 v0 = *(const float2*)(ds + (rbase + gid) * FOUT + col);
            float2 v1 = *(const float2*)(ds + (rbase + gid + 8) * FOUT + col);
            *(float2*)(dp + (size_t)(rbase + gid) * FOUT + col) =
                make_float2(acc[i][0] + v0.x, acc[i][1] + v0.y);
            *(float2*)(dp + (size_t)(rbase + gid + 8) * FOUT + col) =
                make_float2(acc[i][2] + v1.x, acc[i][3] + v1.y);
        }
        if (tid == 0) {
            g_l[split * NT + ibase + rbase + gid] = acc_l[0] + lr[rbase + gid];
            g_l[split * NT + ibase + rbase + gid + 8] = acc_l[2] + lr[rbase + gid + 8];
        }
    }
}

// ---------------------------------------------------------------------------
__global__ void combine(float* __restrict__ out) {
    int base = (blockIdx.x * 256 + threadIdx.x) * 2;
#pragma unroll
    for (int u = 0; u < 2; u++) {
        int idx = base + u;
        int r = idx >> 4, c4 = idx & 15;
        float4 d0 = *(const float4*)(g_Dp + (size_t)r * FOUT + c4 * 4);
        float4 d1 = *(const float4*)(g_Dp + ((size_t)NT + r) * FOUT + c4 * 4);
        float inv = 1.f / (g_l[r] + g_l[NT + r]);
        float v[4] = {(d0.x + d1.x) * inv, (d0.y + d1.y) * inv,
                      (d0.z + d1.z) * inv, (d0.w + d1.w) * inv};
#pragma unroll
        for (int i = 0; i < 4; i++) v[i] = v[i] > 0.f ? v[i] : expm1f(v[i]);
        *(float4*)(out + (size_t)r * FOUT + c4 * 4) =
            make_float4(v[0], v[1], v[2], v[3]);
    }
}

// ---------------------------------------------------------------------------
extern "C" void kernel_launch(void* const* d_in, const int* in_sizes, int n_in,
                              void* d_out, int out_size) {
    const float* t_input = (const float*)d_in[0];
    const float* o_input = (const float*)d_in[1];
    const float* W_t     = (const float*)d_in[2];
    const float* W_o     = (const float*)d_in[3];
    const float* a       = (const float*)d_in[4];
    const int*   adj     = (const int*)d_in[5];
    float* out = (float*)d_out;

    cudaFuncSetAttribute(attn_main, cudaFuncAttributeMaxDynamicSharedMemorySize,
                         SM_TOTAL);

    prep_w<<<1, 256>>>(W_t, a);
    prep_hoT<<<NO / 32, 256>>>(o_input, W_o, a);
    attn_main<<<dim3(NT / BM, KSPLIT), THREADS, SM_TOTAL>>>(t_input, adj);
    combine<<<NT * FOUT / 8 / 256, 256>>>(out);
}